// round 10
// baseline (speedup 1.0000x reference)
#include <cuda_runtime.h>
#include <cuda_fp16.h>
#include <mma.h>
#include <cstdint>

using namespace nvcuda;

// Problem constants
#define NTOK 4096
#define KTOP 64
#define DDIM 1024
#define LLAT 16384

// ===================== device globals =====================
__device__ float  g_colpart[8][DDIM];     // ystats column partials (by row-chunk)
__device__ float  g_y2part[64];           // ystats y^2 partials
__device__ float  g_e2part[4096];         // combine e^2 partials (per block)
__device__ float  g_dec[(size_t)NTOK * DDIM];           // decoder contribution
__device__ float  g_sae_fallback[(size_t)NTOK * DDIM];

// fp16 copies
__device__ __half g_xh [(size_t)NTOK * DDIM];   // x
__device__ __half g_wh [(size_t)DDIM * DDIM];   // W_skip
__device__ __half g_wdh[(size_t)LLAT * DDIM];   // W_dec

// ===================== helpers =====================
__device__ __forceinline__ uint32_t smem_u32(const void* p) {
    uint32_t a;
    asm("{ .reg .u64 t; cvta.to.shared.u64 t, %1; cvt.u32.u64 %0, t; }" : "=r"(a) : "l"(p));
    return a;
}
#define CP_ASYNC16(dst_u32, src_ptr) \
    asm volatile("cp.async.cg.shared.global [%0], [%1], 16;" :: "r"(dst_u32), "l"(src_ptr))
#define CP_ASYNC_COMMIT() asm volatile("cp.async.commit_group;")
#define CP_ASYNC_WAIT1()  asm volatile("cp.async.wait_group 1;")
#define CP_ASYNC_WAIT0()  asm volatile("cp.async.wait_group 0;")

// ===================== fp32 -> fp16 convert (64B per thread) =====================
__global__ __launch_bounds__(256) void k_tohalf4(const float* __restrict__ src,
                                                 __half* __restrict__ dst, int n16) {
    // each thread converts 4 float4 = 16 floats
    int i = blockIdx.x * blockDim.x + threadIdx.x;
    if (i >= n16) return;
    const float4* s4 = (const float4*)src + (size_t)i * 4;
    uint2* d2 = (uint2*)dst + (size_t)i * 4;
#pragma unroll
    for (int j = 0; j < 4; j++) {
        float4 v = s4[j];
        __half2 lo = __floats2half2_rn(v.x, v.y);
        __half2 hi = __floats2half2_rn(v.z, v.w);
        uint2 o;
        o.x = *(uint32_t*)&lo;
        o.y = *(uint32_t*)&hi;
        d2[j] = o;
    }
}

// ===================== y column stats (no atomics, partials) =====================
__global__ void k_ystats(const float* __restrict__ y) {
    int d  = blockIdx.x * 128 + threadIdx.x;
    int r0 = blockIdx.y * 512;
    const float* p = y + (size_t)r0 * DDIM + d;
    float s = 0.0f, s2 = 0.0f;
#pragma unroll 8
    for (int r = 0; r < 512; r++) {
        float v = p[(size_t)r * DDIM];
        s  += v;
        s2 += v * v;
    }
    g_colpart[blockIdx.y][d] = s;
    __shared__ float sh[128];
    sh[threadIdx.x] = s2;
    __syncthreads();
    for (int o = 64; o > 0; o >>= 1) {
        if (threadIdx.x < o) sh[threadIdx.x] += sh[threadIdx.x + o];
        __syncthreads();
    }
    if (threadIdx.x == 0) g_y2part[blockIdx.y * 8 + blockIdx.x] = sh[0];
}

// ===================== WMMA fp16 single-pass skip GEMM =====================
#define BM 128
#define BN 128
#define BK 64
#define NKB (DDIM / BK)          // 16
#define LDS_PAD 72
#define MAT_BYTES (128 * LDS_PAD * 2)
#define A_OFF 0
#define B_OFF (MAT_BYTES)
#define STAGE_BYTES (2 * MAT_BYTES)
#define GEMM_SMEM (2 * STAGE_BYTES)

__device__ __forceinline__ void load_stage(
    uint32_t st_u32,
    const __half* __restrict__ A, const __half* __restrict__ B,
    int bm, int bn, int kb, int tid)
{
    const int k0 = kb * BK;
#pragma unroll
    for (int i = 0; i < 4; i++) {
        int idx  = i * 256 + tid;
        int row  = idx >> 3;
        int unit = idx & 7;
        uint32_t dst = st_u32 + row * (LDS_PAD * 2) + unit * 16;
        CP_ASYNC16(dst + A_OFF, A + ((size_t)(bm + row) * DDIM + k0 + unit * 8));
        CP_ASYNC16(dst + B_OFF, B + ((size_t)(bn + row) * DDIM + k0 + unit * 8));
    }
}

__global__ __launch_bounds__(256, 2) void k_skip_gemm_wmma(
    const __half* __restrict__ A, const __half* __restrict__ B,
    float* __restrict__ C)
{
    extern __shared__ char smem[];
    const int tid = threadIdx.x;
    const int wid = tid >> 5;
    const int wm  = wid >> 1;
    const int wn  = wid & 1;
    const int bm  = blockIdx.y * BM;
    const int bn  = blockIdx.x * BN;
    const uint32_t smem32 = smem_u32(smem);

    wmma::fragment<wmma::accumulator, 16, 16, 16, float> acc[2][4];
#pragma unroll
    for (int mm = 0; mm < 2; mm++)
#pragma unroll
        for (int nn = 0; nn < 4; nn++)
            wmma::fill_fragment(acc[mm][nn], 0.0f);

    load_stage(smem32, A, B, bm, bn, 0, tid);
    CP_ASYNC_COMMIT();

    for (int kb = 0; kb < NKB; kb++) {
        const int s = kb & 1;
        if (kb + 1 < NKB) {
            const int f = (kb + 1) & 1;
            load_stage(smem32 + f * STAGE_BYTES, A, B, bm, bn, kb + 1, tid);
            CP_ASYNC_COMMIT();
            CP_ASYNC_WAIT1();
        } else {
            CP_ASYNC_WAIT0();
        }
        __syncthreads();

        const __half* As = (const __half*)(smem + s * STAGE_BYTES + A_OFF);
        const __half* Bs = (const __half*)(smem + s * STAGE_BYTES + B_OFF);

#pragma unroll
        for (int kk = 0; kk < 4; kk++) {
            const int k0 = kk * 16;
            wmma::fragment<wmma::matrix_a, 16, 16, 16, __half, wmma::row_major> af[2];
#pragma unroll
            for (int mm = 0; mm < 2; mm++)
                wmma::load_matrix_sync(af[mm], As + (wm * 32 + mm * 16) * LDS_PAD + k0, LDS_PAD);
#pragma unroll
            for (int nn = 0; nn < 4; nn++) {
                wmma::fragment<wmma::matrix_b, 16, 16, 16, __half, wmma::col_major> bf;
                wmma::load_matrix_sync(bf, Bs + (wn * 64 + nn * 16) * LDS_PAD + k0, LDS_PAD);
#pragma unroll
                for (int mm = 0; mm < 2; mm++)
                    wmma::mma_sync(acc[mm][nn], af[mm], bf, acc[mm][nn]);
            }
        }
        __syncthreads();
    }

#pragma unroll
    for (int mm = 0; mm < 2; mm++) {
        const int row0 = bm + wm * 32 + mm * 16;
#pragma unroll
        for (int nn = 0; nn < 4; nn++) {
            const int col0 = bn + wn * 64 + nn * 16;
            wmma::store_matrix_sync(C + (size_t)row0 * DDIM + col0, acc[mm][nn],
                                    DDIM, wmma::mem_row_major);
        }
    }
}

// ===================== decoder gather (fp16 W_dec) -> g_dec (independent of GEMM) =====================
__global__ __launch_bounds__(256) void k_decode_part(
    const float* __restrict__ latent_acts,
    const int*   __restrict__ latent_indices,
    const __half* __restrict__ W_dec,
    const float* __restrict__ b_dec,
    const float* __restrict__ post_enc,
    const float* __restrict__ post_enc_scale,
    float* __restrict__ dec)
{
    const int n = blockIdx.x;
    const int t = threadIdx.x;

    __shared__ float s_act[KTOP];
    __shared__ int   s_idx[KTOP];

    if (t < KTOP) {
        int i = latent_indices[n * KTOP + t];
        s_idx[t] = i;
        s_act[t] = (latent_acts[n * KTOP + t] + post_enc[i]) * post_enc_scale[i];
    }
    __syncthreads();

    const int d = t * 4;
    float4 acc = *(const float4*)(b_dec + d);

#pragma unroll 16
    for (int k = 0; k < KTOP; k++) {
        uint2 wraw = *(const uint2*)(W_dec + (size_t)s_idx[k] * DDIM + d);
        float2 w0 = __half22float2(*(const __half2*)&wraw.x);
        float2 w1 = __half22float2(*(const __half2*)&wraw.y);
        const float a = s_act[k];
        acc.x = fmaf(a, w0.x, acc.x);
        acc.y = fmaf(a, w0.y, acc.y);
        acc.z = fmaf(a, w1.x, acc.z);
        acc.w = fmaf(a, w1.y, acc.w);
    }
    *(float4*)(dec + (size_t)n * DDIM + d) = acc;
}

// ===================== combine: sae = skip + dec; e2 partials =====================
__global__ __launch_bounds__(256) void k_combine(
    float* __restrict__ sae,          // contains skip GEMM result; updated in place
    const float* __restrict__ dec,
    const float* __restrict__ y)
{
    const int i = blockIdx.x * 256 + threadIdx.x;   // float4 index
    float4 c = ((const float4*)sae)[i];
    float4 dv = ((const float4*)dec)[i];
    float4 yv = ((const float4*)y)[i];
    c.x += dv.x; c.y += dv.y; c.z += dv.z; c.w += dv.w;
    ((float4*)sae)[i] = c;
    float ex = yv.x - c.x, ey = yv.y - c.y, ez = yv.z - c.z, ew = yv.w - c.w;
    float e2 = ex * ex + ey * ey + ez * ez + ew * ew;

    __shared__ float sh[256];
    sh[threadIdx.x] = e2;
    __syncthreads();
    for (int o = 128; o > 0; o >>= 1) {
        if (threadIdx.x < o) sh[threadIdx.x] += sh[threadIdx.x + o];
        __syncthreads();
    }
    if (threadIdx.x == 0) g_e2part[blockIdx.x] = sh[0];
}

// ===================== finalize fvu =====================
__global__ void k_finalize(float* __restrict__ out_fvu) {
    __shared__ double sh[256];
    const int t = threadIdx.x;

    // sum of squared column means term
    double cs2 = 0.0;
    for (int d = t; d < DDIM; d += 256) {
        float cs = 0.0f;
#pragma unroll
        for (int b = 0; b < 8; b++) cs += g_colpart[b][d];
        cs2 += (double)cs * (double)cs;
    }
    // y^2
    double y2 = 0.0;
    for (int i = t; i < 64; i += 256) y2 += (double)g_y2part[i];
    // e^2
    double e2 = 0.0;
    for (int i = t; i < 4096; i += 256) e2 += (double)g_e2part[i];

    sh[t] = cs2;
    __syncthreads();
    for (int o = 128; o > 0; o >>= 1) { if (t < o) sh[t] += sh[t + o]; __syncthreads(); }
    double cs2_tot = sh[0];
    __syncthreads();
    sh[t] = y2;
    __syncthreads();
    for (int o = 128; o > 0; o >>= 1) { if (t < o) sh[t] += sh[t + o]; __syncthreads(); }
    double y2_tot = sh[0];
    __syncthreads();
    sh[t] = e2;
    __syncthreads();
    for (int o = 128; o > 0; o >>= 1) { if (t < o) sh[t] += sh[t + o]; __syncthreads(); }
    double e2_tot = sh[0];

    if (t == 0) {
        double tv  = y2_tot - cs2_tot / (double)NTOK;
        out_fvu[0] = (float)(e2_tot / tv);
    }
}

// ===================== launcher =====================
extern "C" void kernel_launch(void* const* d_in, const int* in_sizes, int n_in,
                              void* d_out, int out_size) {
    const float* x   = (const float*)d_in[0];
    const float* y   = (const float*)d_in[1];
    const float* la  = (const float*)d_in[2];
    const int*   li  = (const int*)  d_in[3];
    const float* Wd  = (const float*)d_in[4];
    const float* bd  = (const float*)d_in[5];
    const float* pe  = (const float*)d_in[6];
    const float* pes = (const float*)d_in[7];
    const float* Ws  = (const float*)d_in[8];

    float* out = (float*)d_out;
    const size_t ND = (size_t)NTOK * DDIM;

    float* sae = out;
    float* fvu_out = nullptr;
    if ((size_t)out_size >= ND) {
        sae = out;
        if ((size_t)out_size > ND) fvu_out = out + ND;
    } else {
        void* p = nullptr;
        cudaGetSymbolAddress(&p, g_sae_fallback);
        sae = (float*)p;
        fvu_out = out;
    }

    void *pxh, *pwh, *pwdh, *pdec;
    cudaGetSymbolAddress(&pxh,  g_xh);
    cudaGetSymbolAddress(&pwh,  g_wh);
    cudaGetSymbolAddress(&pwdh, g_wdh);
    cudaGetSymbolAddress(&pdec, g_dec);

    cudaFuncSetAttribute(k_skip_gemm_wmma, cudaFuncAttributeMaxDynamicSharedMemorySize, GEMM_SMEM);

    // Fork a side stream for the capture graph. Host code only runs during
    // correctness + capture (replays re-execute the graph), so the tiny
    // stream/event leak is bounded to those invocations.
    cudaStream_t s2;
    cudaStreamCreateWithFlags(&s2, cudaStreamNonBlocking);
    cudaEvent_t evF, evJ;
    cudaEventCreateWithFlags(&evF, cudaEventDisableTiming);
    cudaEventCreateWithFlags(&evJ, cudaEventDisableTiming);

    cudaEventRecord(evF, 0);
    cudaStreamWaitEvent(s2, evF, 0);

    // side branch: convert W_dec -> fp16, then independent decoder pass
    k_tohalf4<<<(LLAT * DDIM / 16 + 255) / 256, 256, 0, s2>>>(Wd, (__half*)pwdh, LLAT * DDIM / 16);
    k_decode_part<<<NTOK, 256, 0, s2>>>(la, li, (const __half*)pwdh, bd, pe, pes, (float*)pdec);
    cudaEventRecord(evJ, s2);

    // main branch: convert x & W_skip, skip GEMM, y stats
    k_tohalf4<<<(NTOK * DDIM / 16 + 255) / 256, 256>>>(x,  (__half*)pxh, NTOK * DDIM / 16);
    k_tohalf4<<<(DDIM * DDIM / 16 + 255) / 256, 256>>>(Ws, (__half*)pwh, DDIM * DDIM / 16);
    k_skip_gemm_wmma<<<dim3(DDIM / BN, NTOK / BM), 256, GEMM_SMEM>>>(
        (const __half*)pxh, (const __half*)pwh, sae);
    k_ystats<<<dim3(8, 8), 128>>>(y);

    // join, combine, finalize
    cudaStreamWaitEvent(0, evJ, 0);
    k_combine<<<NTOK * DDIM / 4 / 256, 256>>>(sae, (const float*)pdec, y);
    if (fvu_out) k_finalize<<<1, 256>>>(fvu_out);
}